// round 12
// baseline (speedup 1.0000x reference)
#include <cuda_runtime.h>
#include <math.h>
#include <stdint.h>

#define D_MODEL 1024
#define D_FF    4096
#define NE      8
#define CAP     4096
#define BK      64          // halves per K-tile

// ---------------- device scratch (fp16 payloads stored as u32 words) ----------------
__device__ int      g_counts[NE];
__device__ float    g_sumprobs[NE];
__device__ int      g_tokidx[NE * CAP];
__device__ float    g_tokw[NE * CAP];
__device__ unsigned g_xh[(size_t)CAP * D_MODEL / 2];          // fp16 tokens
__device__ unsigned g_w1h[(size_t)NE * D_MODEL * D_FF / 2];   // fp16 w1 [e][k][n]
__device__ unsigned g_w2h[(size_t)NE * D_FF * D_MODEL / 2];   // fp16 w2 [e][k][n]
__device__ unsigned g_hh[(size_t)NE * CAP * D_FF / 2];        // fp16 hidden

__global__ void zero_small_kernel() {
    int t = threadIdx.x;
    if (t < NE) { g_counts[t] = 0; g_sumprobs[t] = 0.0f; }
}

// ---------------- helpers ----------------
__device__ __forceinline__ unsigned pack_h2(float lo, float hi) {
    unsigned u;
    asm("cvt.rn.f16x2.f32 %0, %1, %2;" : "=r"(u) : "f"(hi), "f"(lo));
    return u;
}

__device__ __forceinline__ uint32_t smem_u32(const void* p) {
    uint32_t a;
    asm("{ .reg .u64 t; cvta.to.shared.u64 t, %1; cvt.u32.u64 %0, t; }" : "=r"(a) : "l"(p));
    return a;
}

__device__ __forceinline__ void mma_f16(float c[4],
                                        unsigned a0, unsigned a1, unsigned a2, unsigned a3,
                                        unsigned b0, unsigned b1) {
    asm volatile(
        "mma.sync.aligned.m16n8k16.row.col.f32.f16.f16.f32 "
        "{%0,%1,%2,%3}, {%4,%5,%6,%7}, {%8,%9}, {%0,%1,%2,%3};\n"
        : "+f"(c[0]), "+f"(c[1]), "+f"(c[2]), "+f"(c[3])
        : "r"(a0), "r"(a1), "r"(a2), "r"(a3), "r"(b0), "r"(b1));
}

#define LDMX4(r0, r1, r2, r3, addr) \
    asm volatile("ldmatrix.sync.aligned.m8n8.x4.shared.b16 {%0,%1,%2,%3}, [%4];" \
        : "=r"(r0), "=r"(r1), "=r"(r2), "=r"(r3) : "r"(addr))

#define LDMX4T(r0, r1, r2, r3, addr) \
    asm volatile("ldmatrix.sync.aligned.m8n8.x4.trans.shared.b16 {%0,%1,%2,%3}, [%4];" \
        : "=r"(r0), "=r"(r1), "=r"(r2), "=r"(r3) : "r"(addr))

__device__ __forceinline__ void cp16(uint32_t dst, const void* src) {
    asm volatile("cp.async.cg.shared.global [%0], [%1], 16;" :: "r"(dst), "l"(src));
}
#define CP_COMMIT() asm volatile("cp.async.commit_group;" ::: "memory")
#define CP_WAIT1()  asm volatile("cp.async.wait_group 1;" ::: "memory")

// smem geometry (bytes): ctrl 1KB | A0 A1 A2 | B0 B1 B2   (3-stage ring)
// A row pitch 144B, B row pitch 272B (both % 128 == 16 -> ldmatrix conflict-free)
#define APITCH 144
#define BPITCH 272
#define ABYTES (128 * APITCH)     // 18432
#define BBYTES (BK * BPITCH)      // 17408
#define OFFA(s) (1024 + (s) * ABYTES)
#define OFFB(s) (1024 + 3 * ABYTES + (s) * BBYTES)
#define DYN_BYTES (1024 + 3 * ABYTES + 3 * BBYTES)   // 108544

// ---------------- merged fp16 pre-conversion (dst arrays referenced in device code) ----------------
__global__ void conv_all_kernel(const float* __restrict__ x,
                                const float* __restrict__ w1,
                                const float* __restrict__ w2,
                                size_t n4x, size_t n4w) {
    size_t total = n4x + 2 * n4w;
    size_t i = (size_t)blockIdx.x * blockDim.x + threadIdx.x;
    size_t stride = (size_t)gridDim.x * blockDim.x;
    for (; i < total; i += stride) {
        const float* src; unsigned* dst; size_t j;
        if (i < n4w)            { src = w1; dst = g_w1h; j = i; }
        else if (i < 2 * n4w)   { src = w2; dst = g_w2h; j = i - n4w; }
        else                    { src = x;  dst = g_xh;  j = i - 2 * n4w; }
        float4 v = ((const float4*)src)[j];
        uint2 o;
        o.x = pack_h2(v.x, v.y);
        o.y = pack_h2(v.z, v.w);
        ((uint2*)dst)[j] = o;
    }
}

// ---------------- router ----------------
__global__ void router_kernel(const float* __restrict__ x,
                              const float* __restrict__ rw,
                              const float* __restrict__ rb,
                              int T) {
    __shared__ float s_rw[NE * D_MODEL];
    for (int i = threadIdx.x; i < D_MODEL * NE; i += blockDim.x) {
        int k = i / NE, e = i % NE;
        s_rw[e * D_MODEL + k] = rw[i];
    }
    __syncthreads();

    int warp = threadIdx.x >> 5;
    int lane = threadIdx.x & 31;
    int tok = blockIdx.x * (blockDim.x >> 5) + warp;
    if (tok >= T) return;

    const float* xr = x + (size_t)tok * D_MODEL;
    float acc[NE];
#pragma unroll
    for (int e = 0; e < NE; e++) acc[e] = 0.0f;
    for (int k = lane; k < D_MODEL; k += 32) {
        float xv = xr[k];
#pragma unroll
        for (int e = 0; e < NE; e++) acc[e] += xv * s_rw[e * D_MODEL + k];
    }
#pragma unroll
    for (int e = 0; e < NE; e++) {
#pragma unroll
        for (int off = 16; off > 0; off >>= 1)
            acc[e] += __shfl_xor_sync(0xFFFFFFFFu, acc[e], off);
    }

    if (lane == 0) {
        float logit[NE]; float m = -1e30f;
#pragma unroll
        for (int e = 0; e < NE; e++) { logit[e] = acc[e] + rb[e]; m = fmaxf(m, logit[e]); }
        float p[NE]; float s = 0.0f;
#pragma unroll
        for (int e = 0; e < NE; e++) { p[e] = __expf(logit[e] - m); s += p[e]; }
        float inv = 1.0f / s;
#pragma unroll
        for (int e = 0; e < NE; e++) p[e] *= inv;
#pragma unroll
        for (int e = 0; e < NE; e++) atomicAdd(&g_sumprobs[e], p[e]);

        int i1 = 0; float v1 = p[0];
#pragma unroll
        for (int e = 1; e < NE; e++) if (p[e] > v1) { v1 = p[e]; i1 = e; }
        int i2 = -1; float v2 = -1.0f;
#pragma unroll
        for (int e = 0; e < NE; e++) if (e != i1 && p[e] > v2) { v2 = p[e]; i2 = e; }

        float wn = 1.0f / (v1 + v2);
        int s1 = atomicAdd(&g_counts[i1], 1);
        g_tokidx[i1 * CAP + s1] = tok;  g_tokw[i1 * CAP + s1] = v1 * wn;
        int s2 = atomicAdd(&g_counts[i2], 1);
        g_tokidx[i2 * CAP + s2] = tok;  g_tokw[i2 * CAP + s2] = v2 * wn;
    }
}

// ---------------- FFN1: h = fp16(gelu(X_e @ w1[e] + b1[e])) ----------------
// CTA tile 128x128, 8 warps as 2x4, warp tile 64x32; 3-stage cp.async ring
__global__ __launch_bounds__(256, 2)
void ffn1_kernel(const float* __restrict__ b1) {
    extern __shared__ unsigned smem[];
    int* s_tok = (int*)smem;

    int e = blockIdx.z;
    int count = g_counts[e];
    int row0 = blockIdx.y * 128;
    if (row0 >= count) return;
    int col0 = blockIdx.x * 128;

    int t = threadIdx.x;
    if (t < 128) {
        int gr = row0 + t;
        s_tok[t] = g_tokidx[e * CAP + (gr < count ? gr : count - 1)];
    }
    __syncthreads();

    int lane = t & 31, wid = t >> 5;
    int warp_m = wid >> 2, warp_n = wid & 3;
    int gid = lane >> 2, tig = lane & 3;
    int lrow = (lane & 7) + (lane & 8);      // 0..15
    int lk   = ((lane >> 4) & 1) * 8;        // 0 or 8

    uint32_t sb = smem_u32(smem);

    // staging (cp.async 16B chunks), anchored at stage 0:
    const unsigned* aS[4]; uint32_t aD[4];
    const unsigned* bS[4]; uint32_t bD[4];
    const unsigned* w1e = g_w1h + (size_t)e * (D_MODEL * D_FF / 2) + col0 / 2;
#pragma unroll
    for (int i = 0; i < 4; i++) {
        int cid = t + 256 * i;
        int arow = cid >> 3, ach = cid & 7;
        aS[i] = g_xh + (size_t)s_tok[arow] * (D_MODEL / 2) + ach * 4;
        aD[i] = sb + OFFA(0) + arow * APITCH + ach * 16;
        int brow = cid >> 4, bch = cid & 15;
        bS[i] = w1e + (size_t)brow * (D_FF / 2) + bch * 4;
        bD[i] = sb + OFFB(0) + brow * BPITCH + bch * 16;
    }

    float acc[4][4][4];
#pragma unroll
    for (int i = 0; i < 4; i++)
#pragma unroll
        for (int j = 0; j < 4; j++)
#pragma unroll
            for (int q = 0; q < 4; q++) acc[i][j][q] = 0.0f;

    const int NIT = D_MODEL / BK;   // 16

    // prologue: tiles 0 and 1 -> stages 0 and 1 (one commit group each)
#pragma unroll
    for (int p = 0; p < 2; p++) {
        uint32_t as = p * ABYTES, bs = p * BBYTES;
        int ktw = p * (BK / 2);
#pragma unroll
        for (int i = 0; i < 4; i++) {
            cp16(aD[i] + as, aS[i] + ktw);
            cp16(bD[i] + bs, bS[i] + (size_t)p * BK * (D_FF / 2));
        }
        CP_COMMIT();
    }

    int sc = 0, sl = 2;   // compute stage / load stage
    for (int it = 0; it < NIT; it++) {
        CP_WAIT1();          // tile `it` complete (tile it+1 may be in flight)
        __syncthreads();     // stage sl's previous readers are done
        if (it + 2 < NIT) {
            int ktw = (it + 2) * (BK / 2);
            uint32_t as = sl * ABYTES, bs = sl * BBYTES;
#pragma unroll
            for (int i = 0; i < 4; i++) {
                cp16(aD[i] + as, aS[i] + ktw);
                cp16(bD[i] + bs, bS[i] + (size_t)(it + 2) * BK * (D_FF / 2));
            }
        }
        CP_COMMIT();         // always commit (empty groups at tail keep counts aligned)

        uint32_t sbA = sb + OFFA(sc);
        uint32_t sbB = sb + OFFB(sc);
#pragma unroll
        for (int ks = 0; ks < BK; ks += 16) {
            unsigned af[4][4], bf[4][2];
#pragma unroll
            for (int i = 0; i < 4; i++) {
                int m = warp_m * 64 + i * 16;
                uint32_t ad = sbA + (m + lrow) * APITCH + (ks + lk) * 2;
                LDMX4(af[i][0], af[i][1], af[i][2], af[i][3], ad);
            }
#pragma unroll
            for (int jj = 0; jj < 2; jj++) {
                uint32_t bd = sbB + (ks + lrow) * BPITCH
                            + (warp_n * 32 + jj * 16 + lk) * 2;
                LDMX4T(bf[jj*2][0], bf[jj*2][1], bf[jj*2+1][0], bf[jj*2+1][1], bd);
            }
#pragma unroll
            for (int i = 0; i < 4; i++)
#pragma unroll
                for (int j = 0; j < 4; j++)
                    mma_f16(acc[i][j], af[i][0], af[i][1], af[i][2], af[i][3],
                            bf[j][0], bf[j][1]);
        }
        sc = (sc == 2) ? 0 : sc + 1;
        sl = (sl == 2) ? 0 : sl + 1;
    }

    // epilogue: + b1, exact gelu, fp16 store
#pragma unroll
    for (int i = 0; i < 4; i++) {
        int mrow = warp_m * 64 + i * 16 + gid;
#pragma unroll
        for (int half = 0; half < 2; half++) {
            int gr = row0 + mrow + half * 8;
            if (gr >= count) continue;
            unsigned* hrow = g_hh + ((size_t)e * CAP + gr) * (D_FF / 2) + col0 / 2;
#pragma unroll
            for (int j = 0; j < 4; j++) {
                int c = warp_n * 32 + j * 8 + tig * 2;
                float v0 = acc[i][j][half * 2 + 0] + b1[e * D_FF + col0 + c];
                float v1 = acc[i][j][half * 2 + 1] + b1[e * D_FF + col0 + c + 1];
                float g0 = 0.5f * v0 * (1.0f + erff(v0 * 0.70710678118654752f));
                float g1 = 0.5f * v1 * (1.0f + erff(v1 * 0.70710678118654752f));
                hrow[c / 2] = pack_h2(g0, g1);
            }
        }
    }
}

// ---------------- FFN2: out += w * (h @ w2[e] + b2[e]) ----------------
__global__ __launch_bounds__(256, 2)
void ffn2_kernel(const float* __restrict__ b2, float* __restrict__ out) {
    extern __shared__ unsigned smem[];
    int*   s_tok = (int*)smem;
    float* s_w   = (float*)(smem + 128);

    int e = blockIdx.z;
    int count = g_counts[e];
    int row0 = blockIdx.y * 128;
    if (row0 >= count) return;
    int col0 = blockIdx.x * 128;

    int t = threadIdx.x;
    if (t < 128) {
        int gr = row0 + t;
        int idx = gr < count ? gr : count - 1;
        s_tok[t] = g_tokidx[e * CAP + idx];
        s_w[t]   = (gr < count) ? g_tokw[e * CAP + idx] : 0.0f;
    }
    __syncthreads();

    int lane = t & 31, wid = t >> 5;
    int warp_m = wid >> 2, warp_n = wid & 3;
    int gid = lane >> 2, tig = lane & 3;
    int lrow = (lane & 7) + (lane & 8);
    int lk   = ((lane >> 4) & 1) * 8;

    uint32_t sb = smem_u32(smem);

    const unsigned* he  = g_hh + ((size_t)e * CAP + row0) * (D_FF / 2);
    const unsigned* w2e = g_w2h + (size_t)e * (D_FF * D_MODEL / 2) + col0 / 2;

    const unsigned* aS[4]; uint32_t aD[4];
    const unsigned* bS[4]; uint32_t bD[4];
#pragma unroll
    for (int i = 0; i < 4; i++) {
        int cid = t + 256 * i;
        int arow = cid >> 3, ach = cid & 7;
        aS[i] = he + (size_t)arow * (D_FF / 2) + ach * 4;
        aD[i] = sb + OFFA(0) + arow * APITCH + ach * 16;
        int brow = cid >> 4, bch = cid & 15;
        bS[i] = w2e + (size_t)brow * (D_MODEL / 2) + bch * 4;
        bD[i] = sb + OFFB(0) + brow * BPITCH + bch * 16;
    }

    float acc[4][4][4];
#pragma unroll
    for (int i = 0; i < 4; i++)
#pragma unroll
        for (int j = 0; j < 4; j++)
#pragma unroll
            for (int q = 0; q < 4; q++) acc[i][j][q] = 0.0f;

    const int NIT = D_FF / BK;   // 64

#pragma unroll
    for (int p = 0; p < 2; p++) {
        uint32_t as = p * ABYTES, bs = p * BBYTES;
        int ktw = p * (BK / 2);
#pragma unroll
        for (int i = 0; i < 4; i++) {
            cp16(aD[i] + as, aS[i] + ktw);
            cp16(bD[i] + bs, bS[i] + (size_t)p * BK * (D_MODEL / 2));
        }
        CP_COMMIT();
    }

    int sc = 0, sl = 2;
    for (int it = 0; it < NIT; it++) {
        CP_WAIT1();
        __syncthreads();
        if (it + 2 < NIT) {
            int ktw = (it + 2) * (BK / 2);
            uint32_t as = sl * ABYTES, bs = sl * BBYTES;
#pragma unroll
            for (int i = 0; i < 4; i++) {
                cp16(aD[i] + as, aS[i] + ktw);
                cp16(bD[i] + bs, bS[i] + (size_t)(it + 2) * BK * (D_MODEL / 2));
            }
        }
        CP_COMMIT();

        uint32_t sbA = sb + OFFA(sc);
        uint32_t sbB = sb + OFFB(sc);
#pragma unroll
        for (int ks = 0; ks < BK; ks += 16) {
            unsigned af[4][4], bf[4][2];
#pragma unroll
            for (int i = 0; i < 4; i++) {
                int m = warp_m * 64 + i * 16;
                uint32_t ad = sbA + (m + lrow) * APITCH + (ks + lk) * 2;
                LDMX4(af[i][0], af[i][1], af[i][2], af[i][3], ad);
            }
#pragma unroll
            for (int jj = 0; jj < 2; jj++) {
                uint32_t bd = sbB + (ks + lrow) * BPITCH
                            + (warp_n * 32 + jj * 16 + lk) * 2;
                LDMX4T(bf[jj*2][0], bf[jj*2][1], bf[jj*2+1][0], bf[jj*2+1][1], bd);
            }
#pragma unroll
            for (int i = 0; i < 4; i++)
#pragma unroll
                for (int j = 0; j < 4; j++)
                    mma_f16(acc[i][j], af[i][0], af[i][1], af[i][2], af[i][3],
                            bf[j][0], bf[j][1]);
        }
        sc = (sc == 2) ? 0 : sc + 1;
        sl = (sl == 2) ? 0 : sl + 1;
    }

    // epilogue: weighted atomic scatter
#pragma unroll
    for (int i = 0; i < 4; i++) {
        int mrow = warp_m * 64 + i * 16 + gid;
#pragma unroll
        for (int half = 0; half < 2; half++) {
            int r = mrow + half * 8;
            int gr = row0 + r;
            if (gr >= count) continue;
            int tok = s_tok[r];
            float w  = s_w[r];
            float* orow = out + (size_t)tok * D_MODEL + col0;
#pragma unroll
            for (int j = 0; j < 4; j++) {
                int c = warp_n * 32 + j * 8 + tig * 2;
                float v0 = acc[i][j][half * 2 + 0] + b2[e * D_MODEL + col0 + c];
                float v1 = acc[i][j][half * 2 + 1] + b2[e * D_MODEL + col0 + c + 1];
                atomicAdd(&orow[c],     w * v0);
                atomicAdd(&orow[c + 1], w * v1);
            }
        }
    }
}

// ---------------- aux loss ----------------
__global__ void aux_kernel(float* out_aux, float invT) {
    if (threadIdx.x == 0 && blockIdx.x == 0) {
        float m[NE]; float mu = 0.0f;
#pragma unroll
        for (int e = 0; e < NE; e++) { m[e] = g_sumprobs[e] * invT; mu += m[e]; }
        mu *= (1.0f / NE);
        float v = 0.0f;
#pragma unroll
        for (int e = 0; e < NE; e++) { float d = m[e] - mu; v += d * d; }
        *out_aux = v / (NE - 1);
    }
}

// ---------------- launch ----------------
extern "C" void kernel_launch(void* const* d_in, const int* in_sizes, int n_in,
                              void* d_out, int out_size) {
    const float* x  = (const float*)d_in[0];
    const float* rw = (const float*)d_in[1];
    const float* rb = (const float*)d_in[2];
    const float* w1 = (const float*)d_in[3];
    const float* b1 = (const float*)d_in[4];
    const float* w2 = (const float*)d_in[5];
    const float* b2 = (const float*)d_in[6];
    float* out = (float*)d_out;

    int T = in_sizes[0] / D_MODEL;

    cudaFuncSetAttribute(ffn1_kernel, cudaFuncAttributeMaxDynamicSharedMemorySize, DYN_BYTES);
    cudaFuncSetAttribute(ffn2_kernel, cudaFuncAttributeMaxDynamicSharedMemorySize, DYN_BYTES);

    cudaMemsetAsync(d_out, 0, (size_t)T * D_MODEL * sizeof(float));
    zero_small_kernel<<<1, 32>>>();
    router_kernel<<<(T + 3) / 4, 128>>>(x, rw, rb, T);

    conv_all_kernel<<<8192, 256>>>(x, w1, w2,
                                   (size_t)T * D_MODEL / 4,
                                   (size_t)NE * D_MODEL * D_FF / 4);

    dim3 g1(D_FF / 128, CAP / 128, NE);
    ffn1_kernel<<<g1, 256, DYN_BYTES>>>(b1);

    dim3 g2(D_MODEL / 128, CAP / 128, NE);
    ffn2_kernel<<<g2, 256, DYN_BYTES>>>(b2, out);

    if (out_size > T * D_MODEL) {
        aux_kernel<<<1, 32>>>(out + (size_t)T * D_MODEL, 1.0f / (float)T);
    }
}

// round 13
// speedup vs baseline: 1.0243x; 1.0243x over previous
#include <cuda_runtime.h>
#include <math.h>
#include <stdint.h>

#define D_MODEL 1024
#define D_FF    4096
#define NE      8
#define CAP     4096
#define BK      64          // halves per K-tile

// ---------------- device scratch (fp16 payloads stored as u32 words) ----------------
__device__ int      g_counts[NE];
__device__ float    g_sumprobs[NE];
__device__ int      g_tokidx[NE * CAP];
__device__ float    g_tokw[NE * CAP];
__device__ unsigned g_xh[(size_t)CAP * D_MODEL / 2];          // fp16 tokens
__device__ unsigned g_w1h[(size_t)NE * D_MODEL * D_FF / 2];   // fp16 w1 [e][k][n]
__device__ unsigned g_w2h[(size_t)NE * D_FF * D_MODEL / 2];   // fp16 w2 [e][k][n]
__device__ unsigned g_hh[(size_t)NE * CAP * D_FF / 2];        // fp16 hidden

// ---------------- helpers ----------------
__device__ __forceinline__ unsigned pack_h2(float lo, float hi) {
    unsigned u;
    asm("cvt.rn.f16x2.f32 %0, %1, %2;" : "=r"(u) : "f"(hi), "f"(lo));
    return u;
}

__device__ __forceinline__ uint32_t smem_u32(const void* p) {
    uint32_t a;
    asm("{ .reg .u64 t; cvta.to.shared.u64 t, %1; cvt.u32.u64 %0, t; }" : "=r"(a) : "l"(p));
    return a;
}

__device__ __forceinline__ void mma_f16(float c[4],
                                        unsigned a0, unsigned a1, unsigned a2, unsigned a3,
                                        unsigned b0, unsigned b1) {
    asm volatile(
        "mma.sync.aligned.m16n8k16.row.col.f32.f16.f16.f32 "
        "{%0,%1,%2,%3}, {%4,%5,%6,%7}, {%8,%9}, {%0,%1,%2,%3};\n"
        : "+f"(c[0]), "+f"(c[1]), "+f"(c[2]), "+f"(c[3])
        : "r"(a0), "r"(a1), "r"(a2), "r"(a3), "r"(b0), "r"(b1));
}

#define LDMX4(r0, r1, r2, r3, addr) \
    asm volatile("ldmatrix.sync.aligned.m8n8.x4.shared.b16 {%0,%1,%2,%3}, [%4];" \
        : "=r"(r0), "=r"(r1), "=r"(r2), "=r"(r3) : "r"(addr))

#define LDMX4T(r0, r1, r2, r3, addr) \
    asm volatile("ldmatrix.sync.aligned.m8n8.x4.trans.shared.b16 {%0,%1,%2,%3}, [%4];" \
        : "=r"(r0), "=r"(r1), "=r"(r2), "=r"(r3) : "r"(addr))

__device__ __forceinline__ void cp16(uint32_t dst, const void* src) {
    asm volatile("cp.async.cg.shared.global [%0], [%1], 16;" :: "r"(dst), "l"(src));
}
#define CP_COMMIT() asm volatile("cp.async.commit_group;" ::: "memory")
#define CP_WAIT0()  asm volatile("cp.async.wait_group 0;" ::: "memory")

// smem geometry (bytes): ctrl 1KB | A0 | A1 | B0 | B1
// A row pitch 144B, B row pitch 272B (both % 128 == 16 -> ldmatrix conflict-free)
#define APITCH 144
#define BPITCH 272
#define ABYTES (128 * APITCH)     // 18432
#define BBYTES (BK * BPITCH)      // 17408
#define OFFA(b) (1024 + (b) * ABYTES)
#define OFFB(b) (1024 + 2 * ABYTES + (b) * BBYTES)
#define DYN_BYTES (1024 + 2 * ABYTES + 2 * BBYTES)   // 72704

// ---------------- merged fp16 pre-conversion + control zeroing ----------------
// Runs BEFORE router; block 0 zeroes counts/sumprobs (no other consumer until router).
__global__ void conv_all_kernel(const float* __restrict__ x,
                                const float* __restrict__ w1,
                                const float* __restrict__ w2,
                                size_t n4x, size_t n4w) {
    if (blockIdx.x == 0 && threadIdx.x < NE) {
        g_counts[threadIdx.x] = 0;
        g_sumprobs[threadIdx.x] = 0.0f;
    }
    size_t total = n4x + 2 * n4w;
    size_t i = (size_t)blockIdx.x * blockDim.x + threadIdx.x;
    size_t stride = (size_t)gridDim.x * blockDim.x;
    for (; i < total; i += stride) {
        const float* src; unsigned* dst; size_t j;
        if (i < n4w)            { src = w1; dst = g_w1h; j = i; }
        else if (i < 2 * n4w)   { src = w2; dst = g_w2h; j = i - n4w; }
        else                    { src = x;  dst = g_xh;  j = i - 2 * n4w; }
        float4 v = ((const float4*)src)[j];
        uint2 o;
        o.x = pack_h2(v.x, v.y);
        o.y = pack_h2(v.z, v.w);
        ((uint2*)dst)[j] = o;
    }
}

// ---------------- router (also zeroes this token's output row) ----------------
__global__ void router_kernel(const float* __restrict__ x,
                              const float* __restrict__ rw,
                              const float* __restrict__ rb,
                              float* __restrict__ out,
                              int T) {
    __shared__ float s_rw[NE * D_MODEL];
    for (int i = threadIdx.x; i < D_MODEL * NE; i += blockDim.x) {
        int k = i / NE, e = i % NE;
        s_rw[e * D_MODEL + k] = rw[i];
    }
    __syncthreads();

    int warp = threadIdx.x >> 5;
    int lane = threadIdx.x & 31;
    int tok = blockIdx.x * (blockDim.x >> 5) + warp;
    if (tok >= T) return;

    // zero this token's output row (replaces the memset launch)
    {
        float4* orow = (float4*)(out + (size_t)tok * D_MODEL);
        float4 z = make_float4(0.f, 0.f, 0.f, 0.f);
#pragma unroll
        for (int i = 0; i < D_MODEL / 4 / 32; i++)
            orow[lane + i * 32] = z;
    }

    const float* xr = x + (size_t)tok * D_MODEL;
    float acc[NE];
#pragma unroll
    for (int e = 0; e < NE; e++) acc[e] = 0.0f;
    for (int k = lane; k < D_MODEL; k += 32) {
        float xv = xr[k];
#pragma unroll
        for (int e = 0; e < NE; e++) acc[e] += xv * s_rw[e * D_MODEL + k];
    }
#pragma unroll
    for (int e = 0; e < NE; e++) {
#pragma unroll
        for (int off = 16; off > 0; off >>= 1)
            acc[e] += __shfl_xor_sync(0xFFFFFFFFu, acc[e], off);
    }

    if (lane == 0) {
        float logit[NE]; float m = -1e30f;
#pragma unroll
        for (int e = 0; e < NE; e++) { logit[e] = acc[e] + rb[e]; m = fmaxf(m, logit[e]); }
        float p[NE]; float s = 0.0f;
#pragma unroll
        for (int e = 0; e < NE; e++) { p[e] = __expf(logit[e] - m); s += p[e]; }
        float inv = 1.0f / s;
#pragma unroll
        for (int e = 0; e < NE; e++) p[e] *= inv;
#pragma unroll
        for (int e = 0; e < NE; e++) atomicAdd(&g_sumprobs[e], p[e]);

        int i1 = 0; float v1 = p[0];
#pragma unroll
        for (int e = 1; e < NE; e++) if (p[e] > v1) { v1 = p[e]; i1 = e; }
        int i2 = -1; float v2 = -1.0f;
#pragma unroll
        for (int e = 0; e < NE; e++) if (e != i1 && p[e] > v2) { v2 = p[e]; i2 = e; }

        float wn = 1.0f / (v1 + v2);
        int s1 = atomicAdd(&g_counts[i1], 1);
        g_tokidx[i1 * CAP + s1] = tok;  g_tokw[i1 * CAP + s1] = v1 * wn;
        int s2 = atomicAdd(&g_counts[i2], 1);
        g_tokidx[i2 * CAP + s2] = tok;  g_tokw[i2 * CAP + s2] = v2 * wn;
    }
}

// ---------------- FFN1: h = fp16(gelu(X_e @ w1[e] + b1[e])); also writes aux ----------------
// CTA tile 128x128, 8 warps as 2x4, warp tile 64x32
__global__ __launch_bounds__(256, 2)
void ffn1_kernel(const float* __restrict__ b1, float* out_aux, float invT) {
    extern __shared__ unsigned smem[];
    int* s_tok = (int*)smem;

    // aux loss (router's g_sumprobs is final; placed BEFORE any early exit)
    if (blockIdx.x == 0 && blockIdx.y == 0 && blockIdx.z == 0 && threadIdx.x == 0
        && out_aux != nullptr) {
        float m[NE]; float mu = 0.0f;
#pragma unroll
        for (int e = 0; e < NE; e++) { m[e] = g_sumprobs[e] * invT; mu += m[e]; }
        mu *= (1.0f / NE);
        float v = 0.0f;
#pragma unroll
        for (int e = 0; e < NE; e++) { float d = m[e] - mu; v += d * d; }
        *out_aux = v / (NE - 1);
    }

    int e = blockIdx.z;
    int count = g_counts[e];
    int row0 = blockIdx.y * 128;
    if (row0 >= count) return;
    int col0 = blockIdx.x * 128;

    int t = threadIdx.x;
    if (t < 128) {
        int gr = row0 + t;
        s_tok[t] = g_tokidx[e * CAP + (gr < count ? gr : count - 1)];
    }
    __syncthreads();

    int lane = t & 31, wid = t >> 5;
    int warp_m = wid >> 2, warp_n = wid & 3;
    int gid = lane >> 2, tig = lane & 3;
    int lrow = (lane & 7) + (lane & 8);      // 0..15
    int lk   = ((lane >> 4) & 1) * 8;        // 0 or 8

    uint32_t sb = smem_u32(smem);

    const unsigned* aS[4]; uint32_t aD[4];
    const unsigned* bS[4]; uint32_t bD[4];
    const unsigned* w1e = g_w1h + (size_t)e * (D_MODEL * D_FF / 2) + col0 / 2;
#pragma unroll
    for (int i = 0; i < 4; i++) {
        int cid = t + 256 * i;
        int arow = cid >> 3, ach = cid & 7;
        aS[i] = g_xh + (size_t)s_tok[arow] * (D_MODEL / 2) + ach * 4;
        aD[i] = sb + OFFA(0) + arow * APITCH + ach * 16;
        int brow = cid >> 4, bch = cid & 15;
        bS[i] = w1e + (size_t)brow * (D_FF / 2) + bch * 4;
        bD[i] = sb + OFFB(0) + brow * BPITCH + bch * 16;
    }

    float acc[4][4][4];
#pragma unroll
    for (int i = 0; i < 4; i++)
#pragma unroll
        for (int j = 0; j < 4; j++)
#pragma unroll
            for (int q = 0; q < 4; q++) acc[i][j][q] = 0.0f;

#pragma unroll
    for (int i = 0; i < 4; i++) { cp16(aD[i], aS[i]); cp16(bD[i], bS[i]); }
    CP_COMMIT();

    const int NIT = D_MODEL / BK;   // 16
    int buf = 0;
    for (int it = 0; it < NIT; it++) {
        CP_WAIT0();
        __syncthreads();
        if (it + 1 < NIT) {
            int ktw = (it + 1) * (BK / 2);
            uint32_t as = (buf ^ 1) * ABYTES;
            uint32_t bs = (buf ^ 1) * BBYTES;
#pragma unroll
            for (int i = 0; i < 4; i++) {
                cp16(aD[i] + as, aS[i] + ktw);
                cp16(bD[i] + bs, bS[i] + (size_t)(it + 1) * BK * (D_FF / 2));
            }
            CP_COMMIT();
        }

        uint32_t sbA = sb + OFFA(buf);
        uint32_t sbB = sb + OFFB(buf);
#pragma unroll
        for (int ks = 0; ks < BK; ks += 16) {
            unsigned af[4][4], bf[4][2];
#pragma unroll
            for (int i = 0; i < 4; i++) {
                int m = warp_m * 64 + i * 16;
                uint32_t ad = sbA + (m + lrow) * APITCH + (ks + lk) * 2;
                LDMX4(af[i][0], af[i][1], af[i][2], af[i][3], ad);
            }
#pragma unroll
            for (int jj = 0; jj < 2; jj++) {
                uint32_t bd = sbB + (ks + lrow) * BPITCH
                            + (warp_n * 32 + jj * 16 + lk) * 2;
                LDMX4T(bf[jj*2][0], bf[jj*2][1], bf[jj*2+1][0], bf[jj*2+1][1], bd);
            }
#pragma unroll
            for (int i = 0; i < 4; i++)
#pragma unroll
                for (int j = 0; j < 4; j++)
                    mma_f16(acc[i][j], af[i][0], af[i][1], af[i][2], af[i][3],
                            bf[j][0], bf[j][1]);
        }
        buf ^= 1;
    }

    // epilogue: + b1, exact gelu, fp16 store
#pragma unroll
    for (int i = 0; i < 4; i++) {
        int mrow = warp_m * 64 + i * 16 + gid;
#pragma unroll
        for (int half = 0; half < 2; half++) {
            int gr = row0 + mrow + half * 8;
            if (gr >= count) continue;
            unsigned* hrow = g_hh + ((size_t)e * CAP + gr) * (D_FF / 2) + col0 / 2;
#pragma unroll
            for (int j = 0; j < 4; j++) {
                int c = warp_n * 32 + j * 8 + tig * 2;
                float v0 = acc[i][j][half * 2 + 0] + b1[e * D_FF + col0 + c];
                float v1 = acc[i][j][half * 2 + 1] + b1[e * D_FF + col0 + c + 1];
                float g0 = 0.5f * v0 * (1.0f + erff(v0 * 0.70710678118654752f));
                float g1 = 0.5f * v1 * (1.0f + erff(v1 * 0.70710678118654752f));
                hrow[c / 2] = pack_h2(g0, g1);
            }
        }
    }
}

// ---------------- FFN2: out += w * (h @ w2[e] + b2[e]) ----------------
__global__ __launch_bounds__(256, 2)
void ffn2_kernel(const float* __restrict__ b2, float* __restrict__ out) {
    extern __shared__ unsigned smem[];
    int*   s_tok = (int*)smem;
    float* s_w   = (float*)(smem + 128);

    int e = blockIdx.z;
    int count = g_counts[e];
    int row0 = blockIdx.y * 128;
    if (row0 >= count) return;
    int col0 = blockIdx.x * 128;

    int t = threadIdx.x;
    if (t < 128) {
        int gr = row0 + t;
        int idx = gr < count ? gr : count - 1;
        s_tok[t] = g_tokidx[e * CAP + idx];
        s_w[t]   = (gr < count) ? g_tokw[e * CAP + idx] : 0.0f;
    }
    __syncthreads();

    int lane = t & 31, wid = t >> 5;
    int warp_m = wid >> 2, warp_n = wid & 3;
    int gid = lane >> 2, tig = lane & 3;
    int lrow = (lane & 7) + (lane & 8);
    int lk   = ((lane >> 4) & 1) * 8;

    uint32_t sb = smem_u32(smem);

    const unsigned* he  = g_hh + ((size_t)e * CAP + row0) * (D_FF / 2);
    const unsigned* w2e = g_w2h + (size_t)e * (D_FF * D_MODEL / 2) + col0 / 2;

    const unsigned* aS[4]; uint32_t aD[4];
    const unsigned* bS[4]; uint32_t bD[4];
#pragma unroll
    for (int i = 0; i < 4; i++) {
        int cid = t + 256 * i;
        int arow = cid >> 3, ach = cid & 7;
        aS[i] = he + (size_t)arow * (D_FF / 2) + ach * 4;
        aD[i] = sb + OFFA(0) + arow * APITCH + ach * 16;
        int brow = cid >> 4, bch = cid & 15;
        bS[i] = w2e + (size_t)brow * (D_MODEL / 2) + bch * 4;
        bD[i] = sb + OFFB(0) + brow * BPITCH + bch * 16;
    }

    float acc[4][4][4];
#pragma unroll
    for (int i = 0; i < 4; i++)
#pragma unroll
        for (int j = 0; j < 4; j++)
#pragma unroll
            for (int q = 0; q < 4; q++) acc[i][j][q] = 0.0f;

#pragma unroll
    for (int i = 0; i < 4; i++) { cp16(aD[i], aS[i]); cp16(bD[i], bS[i]); }
    CP_COMMIT();

    const int NIT = D_FF / BK;   // 64
    int buf = 0;
    for (int it = 0; it < NIT; it++) {
        CP_WAIT0();
        __syncthreads();
        if (it + 1 < NIT) {
            int ktw = (it + 1) * (BK / 2);
            uint32_t as = (buf ^ 1) * ABYTES;
            uint32_t bs = (buf ^ 1) * BBYTES;
#pragma unroll
            for (int i = 0; i < 4; i++) {
                cp16(aD[i] + as, aS[i] + ktw);
                cp16(bD[i] + bs, bS[i] + (size_t)(it + 1) * BK * (D_MODEL / 2));
            }
            CP_COMMIT();
        }

        uint32_t sbA = sb + OFFA(buf);
        uint32_t sbB = sb + OFFB(buf);
#pragma unroll
        for (int ks = 0; ks < BK; ks += 16) {
            unsigned af[4][4], bf[4][2];
#pragma unroll
            for (int i = 0; i < 4; i++) {
                int m = warp_m * 64 + i * 16;
                uint32_t ad = sbA + (m + lrow) * APITCH + (ks + lk) * 2;
                LDMX4(af[i][0], af[i][1], af[i][2], af[i][3], ad);
            }
#pragma unroll
            for (int jj = 0; jj < 2; jj++) {
                uint32_t bd = sbB + (ks + lrow) * BPITCH
                            + (warp_n * 32 + jj * 16 + lk) * 2;
                LDMX4T(bf[jj*2][0], bf[jj*2][1], bf[jj*2+1][0], bf[jj*2+1][1], bd);
            }
#pragma unroll
            for (int i = 0; i < 4; i++)
#pragma unroll
                for (int j = 0; j < 4; j++)
                    mma_f16(acc[i][j], af[i][0], af[i][1], af[i][2], af[i][3],
                            bf[j][0], bf[j][1]);
        }
        buf ^= 1;
    }

    // epilogue: weighted atomic scatter
#pragma unroll
    for (int i = 0; i < 4; i++) {
        int mrow = warp_m * 64 + i * 16 + gid;
#pragma unroll
        for (int half = 0; half < 2; half++) {
            int r = mrow + half * 8;
            int gr = row0 + r;
            if (gr >= count) continue;
            int tok = s_tok[r];
            float w  = s_w[r];
            float* orow = out + (size_t)tok * D_MODEL + col0;
#pragma unroll
            for (int j = 0; j < 4; j++) {
                int c = warp_n * 32 + j * 8 + tig * 2;
                float v0 = acc[i][j][half * 2 + 0] + b2[e * D_MODEL + col0 + c];
                float v1 = acc[i][j][half * 2 + 1] + b2[e * D_MODEL + col0 + c + 1];
                atomicAdd(&orow[c],     w * v0);
                atomicAdd(&orow[c + 1], w * v1);
            }
        }
    }
}

// ---------------- launch ----------------
extern "C" void kernel_launch(void* const* d_in, const int* in_sizes, int n_in,
                              void* d_out, int out_size) {
    const float* x  = (const float*)d_in[0];
    const float* rw = (const float*)d_in[1];
    const float* rb = (const float*)d_in[2];
    const float* w1 = (const float*)d_in[3];
    const float* b1 = (const float*)d_in[4];
    const float* w2 = (const float*)d_in[5];
    const float* b2 = (const float*)d_in[6];
    float* out = (float*)d_out;

    int T = in_sizes[0] / D_MODEL;

    cudaFuncSetAttribute(ffn1_kernel, cudaFuncAttributeMaxDynamicSharedMemorySize, DYN_BYTES);
    cudaFuncSetAttribute(ffn2_kernel, cudaFuncAttributeMaxDynamicSharedMemorySize, DYN_BYTES);

    // 1) conv (+ zero counts/sumprobs)
    conv_all_kernel<<<8192, 256>>>(x, w1, w2,
                                   (size_t)T * D_MODEL / 4,
                                   (size_t)NE * D_MODEL * D_FF / 4);

    // 2) router (+ zero output rows)
    router_kernel<<<(T + 3) / 4, 128>>>(x, rw, rb, out, T);

    // 3) ffn1 (+ aux loss)
    float* aux_ptr = (out_size > T * D_MODEL) ? (out + (size_t)T * D_MODEL) : nullptr;
    dim3 g1(D_FF / 128, CAP / 128, NE);
    ffn1_kernel<<<g1, 256, DYN_BYTES>>>(b1, aux_ptr, 1.0f / (float)T);

    // 4) ffn2
    dim3 g2(D_MODEL / 128, CAP / 128, NE);
    ffn2_kernel<<<g2, 256, DYN_BYTES>>>(b2, out);
}

// round 14
// speedup vs baseline: 1.0429x; 1.0181x over previous
#include <cuda_runtime.h>
#include <math.h>
#include <stdint.h>

#define D_MODEL 1024
#define D_FF    4096
#define NE      8
#define CAP     4096
#define BK      64          // halves per K-tile

// ---------------- device scratch ----------------
// g_ctrl: [0..7] int counts, [8..15] float sumprobs (single symbol -> one memset)
__device__ __align__(64) unsigned g_ctrl[16];
__device__ int      g_tokidx[NE * CAP];
__device__ float    g_tokw[NE * CAP];
__device__ unsigned g_xh[(size_t)CAP * D_MODEL / 2];          // fp16 tokens
__device__ unsigned g_w1h[(size_t)NE * D_MODEL * D_FF / 2];   // fp16 w1 [e][k][n]
__device__ unsigned g_w2h[(size_t)NE * D_FF * D_MODEL / 2];   // fp16 w2 [e][k][n]
__device__ unsigned g_hh[(size_t)NE * CAP * D_FF / 2];        // fp16 hidden

#define G_COUNTS   ((int*)g_ctrl)
#define G_SUMPROBS (((float*)g_ctrl) + 8)

// ---------------- helpers ----------------
__device__ __forceinline__ unsigned pack_h2(float lo, float hi) {
    unsigned u;
    asm("cvt.rn.f16x2.f32 %0, %1, %2;" : "=r"(u) : "f"(hi), "f"(lo));
    return u;
}

__device__ __forceinline__ uint32_t smem_u32(const void* p) {
    uint32_t a;
    asm("{ .reg .u64 t; cvta.to.shared.u64 t, %1; cvt.u32.u64 %0, t; }" : "=r"(a) : "l"(p));
    return a;
}

__device__ __forceinline__ void mma_f16(float c[4],
                                        unsigned a0, unsigned a1, unsigned a2, unsigned a3,
                                        unsigned b0, unsigned b1) {
    asm volatile(
        "mma.sync.aligned.m16n8k16.row.col.f32.f16.f16.f32 "
        "{%0,%1,%2,%3}, {%4,%5,%6,%7}, {%8,%9}, {%0,%1,%2,%3};\n"
        : "+f"(c[0]), "+f"(c[1]), "+f"(c[2]), "+f"(c[3])
        : "r"(a0), "r"(a1), "r"(a2), "r"(a3), "r"(b0), "r"(b1));
}

#define LDMX4(r0, r1, r2, r3, addr) \
    asm volatile("ldmatrix.sync.aligned.m8n8.x4.shared.b16 {%0,%1,%2,%3}, [%4];" \
        : "=r"(r0), "=r"(r1), "=r"(r2), "=r"(r3) : "r"(addr))

#define LDMX4T(r0, r1, r2, r3, addr) \
    asm volatile("ldmatrix.sync.aligned.m8n8.x4.trans.shared.b16 {%0,%1,%2,%3}, [%4];" \
        : "=r"(r0), "=r"(r1), "=r"(r2), "=r"(r3) : "r"(addr))

__device__ __forceinline__ void cp16(uint32_t dst, const void* src) {
    asm volatile("cp.async.cg.shared.global [%0], [%1], 16;" :: "r"(dst), "l"(src));
}
#define CP_COMMIT() asm volatile("cp.async.commit_group;" ::: "memory")
#define CP_WAIT0()  asm volatile("cp.async.wait_group 0;" ::: "memory")

// smem geometry (bytes): ctrl 1KB | A0 | A1 | B0 | B1
#define APITCH 144
#define BPITCH 272
#define ABYTES (128 * APITCH)     // 18432
#define BBYTES (BK * BPITCH)      // 17408
#define OFFA(b) (1024 + (b) * ABYTES)
#define OFFB(b) (1024 + 2 * ABYTES + (b) * BBYTES)
#define DYN_BYTES (1024 + 2 * ABYTES + 2 * BBYTES)   // 72704

// ---------------- merged router + fp16 conversion ----------------
// Blocks [0, nRouterBlocks): router, 8 warps = 8 tokens per block.
// Blocks [nRouterBlocks, ...): grid-stride fp16 conversion of w1 | w2 | x.
// Counters are zeroed by a preceding cudaMemsetAsync graph node.
__global__ void conv_router_kernel(const float* __restrict__ x,
                                   const float* __restrict__ rw,
                                   const float* __restrict__ rb,
                                   const float* __restrict__ w1,
                                   const float* __restrict__ w2,
                                   float* __restrict__ out,
                                   int T, int nRouterBlocks,
                                   size_t n4x, size_t n4w) {
    if (blockIdx.x < (unsigned)nRouterBlocks) {
        // -------- router part --------
        __shared__ float s_rw[NE * D_MODEL];
        for (int i = threadIdx.x; i < D_MODEL * NE; i += blockDim.x) {
            int k = i / NE, e = i % NE;
            s_rw[e * D_MODEL + k] = rw[i];
        }
        __syncthreads();

        int warp = threadIdx.x >> 5;
        int lane = threadIdx.x & 31;
        int tok = blockIdx.x * 8 + warp;
        if (tok >= T) return;

        // zero this token's output row (replaces memset of out)
        {
            float4* orow = (float4*)(out + (size_t)tok * D_MODEL);
            float4 z = make_float4(0.f, 0.f, 0.f, 0.f);
#pragma unroll
            for (int i = 0; i < D_MODEL / 4 / 32; i++)
                orow[lane + i * 32] = z;
        }

        const float* xr = x + (size_t)tok * D_MODEL;
        float acc[NE];
#pragma unroll
        for (int e = 0; e < NE; e++) acc[e] = 0.0f;
        for (int k = lane; k < D_MODEL; k += 32) {
            float xv = xr[k];
#pragma unroll
            for (int e = 0; e < NE; e++) acc[e] += xv * s_rw[e * D_MODEL + k];
        }
#pragma unroll
        for (int e = 0; e < NE; e++) {
#pragma unroll
            for (int off = 16; off > 0; off >>= 1)
                acc[e] += __shfl_xor_sync(0xFFFFFFFFu, acc[e], off);
        }

        if (lane == 0) {
            float logit[NE]; float m = -1e30f;
#pragma unroll
            for (int e = 0; e < NE; e++) { logit[e] = acc[e] + rb[e]; m = fmaxf(m, logit[e]); }
            float p[NE]; float s = 0.0f;
#pragma unroll
            for (int e = 0; e < NE; e++) { p[e] = __expf(logit[e] - m); s += p[e]; }
            float inv = 1.0f / s;
#pragma unroll
            for (int e = 0; e < NE; e++) p[e] *= inv;
#pragma unroll
            for (int e = 0; e < NE; e++) atomicAdd(&G_SUMPROBS[e], p[e]);

            int i1 = 0; float v1 = p[0];
#pragma unroll
            for (int e = 1; e < NE; e++) if (p[e] > v1) { v1 = p[e]; i1 = e; }
            int i2 = -1; float v2 = -1.0f;
#pragma unroll
            for (int e = 0; e < NE; e++) if (e != i1 && p[e] > v2) { v2 = p[e]; i2 = e; }

            float wn = 1.0f / (v1 + v2);
            int s1 = atomicAdd(&G_COUNTS[i1], 1);
            g_tokidx[i1 * CAP + s1] = tok;  g_tokw[i1 * CAP + s1] = v1 * wn;
            int s2 = atomicAdd(&G_COUNTS[i2], 1);
            g_tokidx[i2 * CAP + s2] = tok;  g_tokw[i2 * CAP + s2] = v2 * wn;
        }
    } else {
        // -------- conversion part --------
        size_t total = n4x + 2 * n4w;
        size_t nConvBlocks = gridDim.x - nRouterBlocks;
        size_t i = (size_t)(blockIdx.x - nRouterBlocks) * blockDim.x + threadIdx.x;
        size_t stride = nConvBlocks * blockDim.x;
        for (; i < total; i += stride) {
            const float* src; unsigned* dst; size_t j;
            if (i < n4w)            { src = w1; dst = g_w1h; j = i; }
            else if (i < 2 * n4w)   { src = w2; dst = g_w2h; j = i - n4w; }
            else                    { src = x;  dst = g_xh;  j = i - 2 * n4w; }
            float4 v = ((const float4*)src)[j];
            uint2 o;
            o.x = pack_h2(v.x, v.y);
            o.y = pack_h2(v.z, v.w);
            ((uint2*)dst)[j] = o;
        }
    }
}

// ---------------- FFN1: h = fp16(gelu(X_e @ w1[e] + b1[e])); also writes aux ----------------
__global__ __launch_bounds__(256, 2)
void ffn1_kernel(const float* __restrict__ b1, float* out_aux, float invT) {
    extern __shared__ unsigned smem[];
    int* s_tok = (int*)smem;

    if (blockIdx.x == 0 && blockIdx.y == 0 && blockIdx.z == 0 && threadIdx.x == 0
        && out_aux != nullptr) {
        float m[NE]; float mu = 0.0f;
#pragma unroll
        for (int e = 0; e < NE; e++) { m[e] = G_SUMPROBS[e] * invT; mu += m[e]; }
        mu *= (1.0f / NE);
        float v = 0.0f;
#pragma unroll
        for (int e = 0; e < NE; e++) { float d = m[e] - mu; v += d * d; }
        *out_aux = v / (NE - 1);
    }

    int e = blockIdx.z;
    int count = G_COUNTS[e];
    int row0 = blockIdx.y * 128;
    if (row0 >= count) return;
    int col0 = blockIdx.x * 128;

    int t = threadIdx.x;
    if (t < 128) {
        int gr = row0 + t;
        s_tok[t] = g_tokidx[e * CAP + (gr < count ? gr : count - 1)];
    }
    __syncthreads();

    int lane = t & 31, wid = t >> 5;
    int warp_m = wid >> 2, warp_n = wid & 3;
    int gid = lane >> 2, tig = lane & 3;
    int lrow = (lane & 7) + (lane & 8);
    int lk   = ((lane >> 4) & 1) * 8;

    uint32_t sb = smem_u32(smem);

    const unsigned* aS[4]; uint32_t aD[4];
    const unsigned* bS[4]; uint32_t bD[4];
    const unsigned* w1e = g_w1h + (size_t)e * (D_MODEL * D_FF / 2) + col0 / 2;
#pragma unroll
    for (int i = 0; i < 4; i++) {
        int cid = t + 256 * i;
        int arow = cid >> 3, ach = cid & 7;
        aS[i] = g_xh + (size_t)s_tok[arow] * (D_MODEL / 2) + ach * 4;
        aD[i] = sb + OFFA(0) + arow * APITCH + ach * 16;
        int brow = cid >> 4, bch = cid & 15;
        bS[i] = w1e + (size_t)brow * (D_FF / 2) + bch * 4;
        bD[i] = sb + OFFB(0) + brow * BPITCH + bch * 16;
    }

    float acc[4][4][4];
#pragma unroll
    for (int i = 0; i < 4; i++)
#pragma unroll
        for (int j = 0; j < 4; j++)
#pragma unroll
            for (int q = 0; q < 4; q++) acc[i][j][q] = 0.0f;

#pragma unroll
    for (int i = 0; i < 4; i++) { cp16(aD[i], aS[i]); cp16(bD[i], bS[i]); }
    CP_COMMIT();

    const int NIT = D_MODEL / BK;   // 16
    int buf = 0;
    for (int it = 0; it < NIT; it++) {
        CP_WAIT0();
        __syncthreads();
        if (it + 1 < NIT) {
            int ktw = (it + 1) * (BK / 2);
            uint32_t as = (buf ^ 1) * ABYTES;
            uint32_t bs = (buf ^ 1) * BBYTES;
#pragma unroll
            for (int i = 0; i < 4; i++) {
                cp16(aD[i] + as, aS[i] + ktw);
                cp16(bD[i] + bs, bS[i] + (size_t)(it + 1) * BK * (D_FF / 2));
            }
            CP_COMMIT();
        }

        uint32_t sbA = sb + OFFA(buf);
        uint32_t sbB = sb + OFFB(buf);
#pragma unroll
        for (int ks = 0; ks < BK; ks += 16) {
            unsigned af[4][4], bf[4][2];
#pragma unroll
            for (int i = 0; i < 4; i++) {
                int m = warp_m * 64 + i * 16;
                uint32_t ad = sbA + (m + lrow) * APITCH + (ks + lk) * 2;
                LDMX4(af[i][0], af[i][1], af[i][2], af[i][3], ad);
            }
#pragma unroll
            for (int jj = 0; jj < 2; jj++) {
                uint32_t bd = sbB + (ks + lrow) * BPITCH
                            + (warp_n * 32 + jj * 16 + lk) * 2;
                LDMX4T(bf[jj*2][0], bf[jj*2][1], bf[jj*2+1][0], bf[jj*2+1][1], bd);
            }
#pragma unroll
            for (int i = 0; i < 4; i++)
#pragma unroll
                for (int j = 0; j < 4; j++)
                    mma_f16(acc[i][j], af[i][0], af[i][1], af[i][2], af[i][3],
                            bf[j][0], bf[j][1]);
        }
        buf ^= 1;
    }

#pragma unroll
    for (int i = 0; i < 4; i++) {
        int mrow = warp_m * 64 + i * 16 + gid;
#pragma unroll
        for (int half = 0; half < 2; half++) {
            int gr = row0 + mrow + half * 8;
            if (gr >= count) continue;
            unsigned* hrow = g_hh + ((size_t)e * CAP + gr) * (D_FF / 2) + col0 / 2;
#pragma unroll
            for (int j = 0; j < 4; j++) {
                int c = warp_n * 32 + j * 8 + tig * 2;
                float v0 = acc[i][j][half * 2 + 0] + b1[e * D_FF + col0 + c];
                float v1 = acc[i][j][half * 2 + 1] + b1[e * D_FF + col0 + c + 1];
                float g0 = 0.5f * v0 * (1.0f + erff(v0 * 0.70710678118654752f));
                float g1 = 0.5f * v1 * (1.0f + erff(v1 * 0.70710678118654752f));
                hrow[c / 2] = pack_h2(g0, g1);
            }
        }
    }
}

// ---------------- FFN2: out += w * (h @ w2[e] + b2[e]) ----------------
__global__ __launch_bounds__(256, 2)
void ffn2_kernel(const float* __restrict__ b2, float* __restrict__ out) {
    extern __shared__ unsigned smem[];
    int*   s_tok = (int*)smem;
    float* s_w   = (float*)(smem + 128);

    int e = blockIdx.z;
    int count = G_COUNTS[e];
    int row0 = blockIdx.y * 128;
    if (row0 >= count) return;
    int col0 = blockIdx.x * 128;

    int t = threadIdx.x;
    if (t < 128) {
        int gr = row0 + t;
        int idx = gr < count ? gr : count - 1;
        s_tok[t] = g_tokidx[e * CAP + idx];
        s_w[t]   = (gr < count) ? g_tokw[e * CAP + idx] : 0.0f;
    }
    __syncthreads();

    int lane = t & 31, wid = t >> 5;
    int warp_m = wid >> 2, warp_n = wid & 3;
    int gid = lane >> 2, tig = lane & 3;
    int lrow = (lane & 7) + (lane & 8);
    int lk   = ((lane >> 4) & 1) * 8;

    uint32_t sb = smem_u32(smem);

    const unsigned* he  = g_hh + ((size_t)e * CAP + row0) * (D_FF / 2);
    const unsigned* w2e = g_w2h + (size_t)e * (D_FF * D_MODEL / 2) + col0 / 2;

    const unsigned* aS[4]; uint32_t aD[4];
    const unsigned* bS[4]; uint32_t bD[4];
#pragma unroll
    for (int i = 0; i < 4; i++) {
        int cid = t + 256 * i;
        int arow = cid >> 3, ach = cid & 7;
        aS[i] = he + (size_t)arow * (D_FF / 2) + ach * 4;
        aD[i] = sb + OFFA(0) + arow * APITCH + ach * 16;
        int brow = cid >> 4, bch = cid & 15;
        bS[i] = w2e + (size_t)brow * (D_MODEL / 2) + bch * 4;
        bD[i] = sb + OFFB(0) + brow * BPITCH + bch * 16;
    }

    float acc[4][4][4];
#pragma unroll
    for (int i = 0; i < 4; i++)
#pragma unroll
        for (int j = 0; j < 4; j++)
#pragma unroll
            for (int q = 0; q < 4; q++) acc[i][j][q] = 0.0f;

#pragma unroll
    for (int i = 0; i < 4; i++) { cp16(aD[i], aS[i]); cp16(bD[i], bS[i]); }
    CP_COMMIT();

    const int NIT = D_FF / BK;   // 64
    int buf = 0;
    for (int it = 0; it < NIT; it++) {
        CP_WAIT0();
        __syncthreads();
        if (it + 1 < NIT) {
            int ktw = (it + 1) * (BK / 2);
            uint32_t as = (buf ^ 1) * ABYTES;
            uint32_t bs = (buf ^ 1) * BBYTES;
#pragma unroll
            for (int i = 0; i < 4; i++) {
                cp16(aD[i] + as, aS[i] + ktw);
                cp16(bD[i] + bs, bS[i] + (size_t)(it + 1) * BK * (D_MODEL / 2));
            }
            CP_COMMIT();
        }

        uint32_t sbA = sb + OFFA(buf);
        uint32_t sbB = sb + OFFB(buf);
#pragma unroll
        for (int ks = 0; ks < BK; ks += 16) {
            unsigned af[4][4], bf[4][2];
#pragma unroll
            for (int i = 0; i < 4; i++) {
                int m = warp_m * 64 + i * 16;
                uint32_t ad = sbA + (m + lrow) * APITCH + (ks + lk) * 2;
                LDMX4(af[i][0], af[i][1], af[i][2], af[i][3], ad);
            }
#pragma unroll
            for (int jj = 0; jj < 2; jj++) {
                uint32_t bd = sbB + (ks + lrow) * BPITCH
                            + (warp_n * 32 + jj * 16 + lk) * 2;
                LDMX4T(bf[jj*2][0], bf[jj*2][1], bf[jj*2+1][0], bf[jj*2+1][1], bd);
            }
#pragma unroll
            for (int i = 0; i < 4; i++)
#pragma unroll
                for (int j = 0; j < 4; j++)
                    mma_f16(acc[i][j], af[i][0], af[i][1], af[i][2], af[i][3],
                            bf[j][0], bf[j][1]);
        }
        buf ^= 1;
    }

#pragma unroll
    for (int i = 0; i < 4; i++) {
        int mrow = warp_m * 64 + i * 16 + gid;
#pragma unroll
        for (int half = 0; half < 2; half++) {
            int r = mrow + half * 8;
            int gr = row0 + r;
            if (gr >= count) continue;
            int tok = s_tok[r];
            float w  = s_w[r];
            float* orow = out + (size_t)tok * D_MODEL + col0;
#pragma unroll
            for (int j = 0; j < 4; j++) {
                int c = warp_n * 32 + j * 8 + tig * 2;
                float v0 = acc[i][j][half * 2 + 0] + b2[e * D_MODEL + col0 + c];
                float v1 = acc[i][j][half * 2 + 1] + b2[e * D_MODEL + col0 + c + 1];
                atomicAdd(&orow[c],     w * v0);
                atomicAdd(&orow[c + 1], w * v1);
            }
        }
    }
}

// ---------------- launch ----------------
extern "C" void kernel_launch(void* const* d_in, const int* in_sizes, int n_in,
                              void* d_out, int out_size) {
    const float* x  = (const float*)d_in[0];
    const float* rw = (const float*)d_in[1];
    const float* rb = (const float*)d_in[2];
    const float* w1 = (const float*)d_in[3];
    const float* b1 = (const float*)d_in[4];
    const float* w2 = (const float*)d_in[5];
    const float* b2 = (const float*)d_in[6];
    float* out = (float*)d_out;

    int T = in_sizes[0] / D_MODEL;

    cudaFuncSetAttribute(ffn1_kernel, cudaFuncAttributeMaxDynamicSharedMemorySize, DYN_BYTES);
    cudaFuncSetAttribute(ffn2_kernel, cudaFuncAttributeMaxDynamicSharedMemorySize, DYN_BYTES);

    // 1) zero control block (counts + sumprobs) — single 64B memset node
    void* ctrlp = nullptr;
    cudaGetSymbolAddress(&ctrlp, g_ctrl);
    cudaMemsetAsync(ctrlp, 0, 64);

    // 2) merged router + conversion (router blocks first -> overlap with conv)
    int nRouterBlocks = (T + 7) / 8;
    conv_router_kernel<<<nRouterBlocks + 8192, 256>>>(
        x, rw, rb, w1, w2, out, T, nRouterBlocks,
        (size_t)T * D_MODEL / 4, (size_t)NE * D_MODEL * D_FF / 4);

    // 3) ffn1 (+ aux loss)
    float* aux_ptr = (out_size > T * D_MODEL) ? (out + (size_t)T * D_MODEL) : nullptr;
    dim3 g1(D_FF / 128, CAP / 128, NE);
    ffn1_kernel<<<g1, 256, DYN_BYTES>>>(b1, aux_ptr, 1.0f / (float)T);

    // 4) ffn2
    dim3 g2(D_MODEL / 128, CAP / 128, NE);
    ffn2_kernel<<<g2, 256, DYN_BYTES>>>(b2, out);
}

// round 15
// speedup vs baseline: 1.0656x; 1.0218x over previous
#include <cuda_runtime.h>
#include <math.h>
#include <stdint.h>

#define D_MODEL 1024
#define D_FF    4096
#define NE      8
#define CAP     4096
#define BK      64          // halves per K-tile

// ---------------- device scratch ----------------
// g_ctrl: [0..7] int counts, [8..15] float sumprobs (single symbol -> one memset)
__device__ __align__(64) unsigned g_ctrl[16];
__device__ int      g_tokidx[NE * CAP];
__device__ float    g_tokw[NE * CAP];
__device__ unsigned g_xh[(size_t)CAP * D_MODEL / 2];          // fp16 tokens
__device__ unsigned g_w1h[(size_t)NE * D_MODEL * D_FF / 2];   // fp16 w1 [e][k][n]
__device__ unsigned g_w2h[(size_t)NE * D_FF * D_MODEL / 2];   // fp16 w2 [e][k][n]
__device__ unsigned g_hh[(size_t)NE * CAP * D_FF / 2];        // fp16 hidden

#define G_COUNTS   ((int*)g_ctrl)
#define G_SUMPROBS (((float*)g_ctrl) + 8)

// ---------------- helpers ----------------
__device__ __forceinline__ unsigned pack_h2(float lo, float hi) {
    unsigned u;
    asm("cvt.rn.f16x2.f32 %0, %1, %2;" : "=r"(u) : "f"(hi), "f"(lo));
    return u;
}

__device__ __forceinline__ uint32_t smem_u32(const void* p) {
    uint32_t a;
    asm("{ .reg .u64 t; cvta.to.shared.u64 t, %1; cvt.u32.u64 %0, t; }" : "=r"(a) : "l"(p));
    return a;
}

__device__ __forceinline__ void mma_f16(float c[4],
                                        unsigned a0, unsigned a1, unsigned a2, unsigned a3,
                                        unsigned b0, unsigned b1) {
    asm volatile(
        "mma.sync.aligned.m16n8k16.row.col.f32.f16.f16.f32 "
        "{%0,%1,%2,%3}, {%4,%5,%6,%7}, {%8,%9}, {%0,%1,%2,%3};\n"
        : "+f"(c[0]), "+f"(c[1]), "+f"(c[2]), "+f"(c[3])
        : "r"(a0), "r"(a1), "r"(a2), "r"(a3), "r"(b0), "r"(b1));
}

#define LDMX4(r0, r1, r2, r3, addr) \
    asm volatile("ldmatrix.sync.aligned.m8n8.x4.shared.b16 {%0,%1,%2,%3}, [%4];" \
        : "=r"(r0), "=r"(r1), "=r"(r2), "=r"(r3) : "r"(addr))

#define LDMX4T(r0, r1, r2, r3, addr) \
    asm volatile("ldmatrix.sync.aligned.m8n8.x4.trans.shared.b16 {%0,%1,%2,%3}, [%4];" \
        : "=r"(r0), "=r"(r1), "=r"(r2), "=r"(r3) : "r"(addr))

__device__ __forceinline__ void cp16(uint32_t dst, const void* src) {
    asm volatile("cp.async.cg.shared.global [%0], [%1], 16;" :: "r"(dst), "l"(src));
}
#define CP_COMMIT() asm volatile("cp.async.commit_group;" ::: "memory")
#define CP_WAIT0()  asm volatile("cp.async.wait_group 0;" ::: "memory")

// smem geometry (bytes): ctrl 1KB | A0 | A1 | B0 | B1
#define APITCH 144
#define BPITCH 272
#define ABYTES (128 * APITCH)     // 18432
#define BBYTES (BK * BPITCH)      // 17408
#define OFFA(b) (1024 + (b) * ABYTES)
#define OFFB(b) (1024 + 2 * ABYTES + (b) * BBYTES)
#define DYN_BYTES (1024 + 2 * ABYTES + 2 * BBYTES)   // 72704

// ---------------- merged router + fp16 conversion (ZERO shared memory) ----------------
// Blocks [0, nRouterBlocks): router, 8 warps = 8 tokens per block; rw read via L1/L2.
// Blocks [nRouterBlocks, ...): grid-stride fp16 conversion of w1 | w2 | x.
// Counters zeroed by a preceding cudaMemsetAsync node.
__global__ void conv_router_kernel(const float* __restrict__ x,
                                   const float* __restrict__ rw,
                                   const float* __restrict__ rb,
                                   const float* __restrict__ w1,
                                   const float* __restrict__ w2,
                                   float* __restrict__ out,
                                   int T, int nRouterBlocks,
                                   size_t n4x, size_t n4w) {
    if (blockIdx.x < (unsigned)nRouterBlocks) {
        // -------- router part (no smem; rw is L2-resident, 32KB) --------
        int warp = threadIdx.x >> 5;
        int lane = threadIdx.x & 31;
        int tok = blockIdx.x * 8 + warp;
        if (tok >= T) return;

        // zero this token's output row (replaces memset of out)
        {
            float4* orow = (float4*)(out + (size_t)tok * D_MODEL);
            float4 z = make_float4(0.f, 0.f, 0.f, 0.f);
#pragma unroll
            for (int i = 0; i < D_MODEL / 4 / 32; i++)
                orow[lane + i * 32] = z;
        }

        const float* xr = x + (size_t)tok * D_MODEL;
        float acc[NE];
#pragma unroll
        for (int e = 0; e < NE; e++) acc[e] = 0.0f;
        // per-lane k: read rw[k*8 .. k*8+8) = 32B; warp reads 1KB contiguous per step.
        for (int k = lane; k < D_MODEL; k += 32) {
            float xv = xr[k];
            float4 r0 = __ldg((const float4*)(rw + (size_t)k * NE));
            float4 r1 = __ldg((const float4*)(rw + (size_t)k * NE + 4));
            acc[0] += xv * r0.x; acc[1] += xv * r0.y;
            acc[2] += xv * r0.z; acc[3] += xv * r0.w;
            acc[4] += xv * r1.x; acc[5] += xv * r1.y;
            acc[6] += xv * r1.z; acc[7] += xv * r1.w;
        }
#pragma unroll
        for (int e = 0; e < NE; e++) {
#pragma unroll
            for (int off = 16; off > 0; off >>= 1)
                acc[e] += __shfl_xor_sync(0xFFFFFFFFu, acc[e], off);
        }

        if (lane == 0) {
            float logit[NE]; float m = -1e30f;
#pragma unroll
            for (int e = 0; e < NE; e++) { logit[e] = acc[e] + rb[e]; m = fmaxf(m, logit[e]); }
            float p[NE]; float s = 0.0f;
#pragma unroll
            for (int e = 0; e < NE; e++) { p[e] = __expf(logit[e] - m); s += p[e]; }
            float inv = 1.0f / s;
#pragma unroll
            for (int e = 0; e < NE; e++) p[e] *= inv;
#pragma unroll
            for (int e = 0; e < NE; e++) atomicAdd(&G_SUMPROBS[e], p[e]);

            int i1 = 0; float v1 = p[0];
#pragma unroll
            for (int e = 1; e < NE; e++) if (p[e] > v1) { v1 = p[e]; i1 = e; }
            int i2 = -1; float v2 = -1.0f;
#pragma unroll
            for (int e = 0; e < NE; e++) if (e != i1 && p[e] > v2) { v2 = p[e]; i2 = e; }

            float wn = 1.0f / (v1 + v2);
            int s1 = atomicAdd(&G_COUNTS[i1], 1);
            g_tokidx[i1 * CAP + s1] = tok;  g_tokw[i1 * CAP + s1] = v1 * wn;
            int s2 = atomicAdd(&G_COUNTS[i2], 1);
            g_tokidx[i2 * CAP + s2] = tok;  g_tokw[i2 * CAP + s2] = v2 * wn;
        }
    } else {
        // -------- conversion part --------
        size_t total = n4x + 2 * n4w;
        size_t nConvBlocks = gridDim.x - nRouterBlocks;
        size_t i = (size_t)(blockIdx.x - nRouterBlocks) * blockDim.x + threadIdx.x;
        size_t stride = nConvBlocks * blockDim.x;
        for (; i < total; i += stride) {
            const float* src; unsigned* dst; size_t j;
            if (i < n4w)            { src = w1; dst = g_w1h; j = i; }
            else if (i < 2 * n4w)   { src = w2; dst = g_w2h; j = i - n4w; }
            else                    { src = x;  dst = g_xh;  j = i - 2 * n4w; }
            float4 v = ((const float4*)src)[j];
            uint2 o;
            o.x = pack_h2(v.x, v.y);
            o.y = pack_h2(v.z, v.w);
            ((uint2*)dst)[j] = o;
        }
    }
}

// ---------------- FFN1: h = fp16(gelu(X_e @ w1[e] + b1[e])); also writes aux ----------------
__global__ __launch_bounds__(256, 2)
void ffn1_kernel(const float* __restrict__ b1, float* out_aux, float invT) {
    extern __shared__ unsigned smem[];
    int* s_tok = (int*)smem;

    if (blockIdx.x == 0 && blockIdx.y == 0 && blockIdx.z == 0 && threadIdx.x == 0
        && out_aux != nullptr) {
        float m[NE]; float mu = 0.0f;
#pragma unroll
        for (int e = 0; e < NE; e++) { m[e] = G_SUMPROBS[e] * invT; mu += m[e]; }
        mu *= (1.0f / NE);
        float v = 0.0f;
#pragma unroll
        for (int e = 0; e < NE; e++) { float d = m[e] - mu; v += d * d; }
        *out_aux = v / (NE - 1);
    }

    int e = blockIdx.z;
    int count = G_COUNTS[e];
    int row0 = blockIdx.y * 128;
    if (row0 >= count) return;
    int col0 = blockIdx.x * 128;

    int t = threadIdx.x;
    if (t < 128) {
        int gr = row0 + t;
        s_tok[t] = g_tokidx[e * CAP + (gr < count ? gr : count - 1)];
    }
    __syncthreads();

    int lane = t & 31, wid = t >> 5;
    int warp_m = wid >> 2, warp_n = wid & 3;
    int gid = lane >> 2, tig = lane & 3;
    int lrow = (lane & 7) + (lane & 8);
    int lk   = ((lane >> 4) & 1) * 8;

    uint32_t sb = smem_u32(smem);

    const unsigned* aS[4]; uint32_t aD[4];
    const unsigned* bS[4]; uint32_t bD[4];
    const unsigned* w1e = g_w1h + (size_t)e * (D_MODEL * D_FF / 2) + col0 / 2;
#pragma unroll
    for (int i = 0; i < 4; i++) {
        int cid = t + 256 * i;
        int arow = cid >> 3, ach = cid & 7;
        aS[i] = g_xh + (size_t)s_tok[arow] * (D_MODEL / 2) + ach * 4;
        aD[i] = sb + OFFA(0) + arow * APITCH + ach * 16;
        int brow = cid >> 4, bch = cid & 15;
        bS[i] = w1e + (size_t)brow * (D_FF / 2) + bch * 4;
        bD[i] = sb + OFFB(0) + brow * BPITCH + bch * 16;
    }

    float acc[4][4][4];
#pragma unroll
    for (int i = 0; i < 4; i++)
#pragma unroll
        for (int j = 0; j < 4; j++)
#pragma unroll
            for (int q = 0; q < 4; q++) acc[i][j][q] = 0.0f;

#pragma unroll
    for (int i = 0; i < 4; i++) { cp16(aD[i], aS[i]); cp16(bD[i], bS[i]); }
    CP_COMMIT();

    const int NIT = D_MODEL / BK;   // 16
    int buf = 0;
    for (int it = 0; it < NIT; it++) {
        CP_WAIT0();
        __syncthreads();
        if (it + 1 < NIT) {
            int ktw = (it + 1) * (BK / 2);
            uint32_t as = (buf ^ 1) * ABYTES;
            uint32_t bs = (buf ^ 1) * BBYTES;
#pragma unroll
            for (int i = 0; i < 4; i++) {
                cp16(aD[i] + as, aS[i] + ktw);
                cp16(bD[i] + bs, bS[i] + (size_t)(it + 1) * BK * (D_FF / 2));
            }
            CP_COMMIT();
        }

        uint32_t sbA = sb + OFFA(buf);
        uint32_t sbB = sb + OFFB(buf);
#pragma unroll
        for (int ks = 0; ks < BK; ks += 16) {
            unsigned af[4][4], bf[4][2];
#pragma unroll
            for (int i = 0; i < 4; i++) {
                int m = warp_m * 64 + i * 16;
                uint32_t ad = sbA + (m + lrow) * APITCH + (ks + lk) * 2;
                LDMX4(af[i][0], af[i][1], af[i][2], af[i][3], ad);
            }
#pragma unroll
            for (int jj = 0; jj < 2; jj++) {
                uint32_t bd = sbB + (ks + lrow) * BPITCH
                            + (warp_n * 32 + jj * 16 + lk) * 2;
                LDMX4T(bf[jj*2][0], bf[jj*2][1], bf[jj*2+1][0], bf[jj*2+1][1], bd);
            }
#pragma unroll
            for (int i = 0; i < 4; i++)
#pragma unroll
                for (int j = 0; j < 4; j++)
                    mma_f16(acc[i][j], af[i][0], af[i][1], af[i][2], af[i][3],
                            bf[j][0], bf[j][1]);
        }
        buf ^= 1;
    }

#pragma unroll
    for (int i = 0; i < 4; i++) {
        int mrow = warp_m * 64 + i * 16 + gid;
#pragma unroll
        for (int half = 0; half < 2; half++) {
            int gr = row0 + mrow + half * 8;
            if (gr >= count) continue;
            unsigned* hrow = g_hh + ((size_t)e * CAP + gr) * (D_FF / 2) + col0 / 2;
#pragma unroll
            for (int j = 0; j < 4; j++) {
                int c = warp_n * 32 + j * 8 + tig * 2;
                float v0 = acc[i][j][half * 2 + 0] + b1[e * D_FF + col0 + c];
                float v1 = acc[i][j][half * 2 + 1] + b1[e * D_FF + col0 + c + 1];
                float g0 = 0.5f * v0 * (1.0f + erff(v0 * 0.70710678118654752f));
                float g1 = 0.5f * v1 * (1.0f + erff(v1 * 0.70710678118654752f));
                hrow[c / 2] = pack_h2(g0, g1);
            }
        }
    }
}

// ---------------- FFN2: out += w * (h @ w2[e] + b2[e]) ----------------
__global__ __launch_bounds__(256, 2)
void ffn2_kernel(const float* __restrict__ b2, float* __restrict__ out) {
    extern __shared__ unsigned smem[];
    int*   s_tok = (int*)smem;
    float* s_w   = (float*)(smem + 128);

    int e = blockIdx.z;
    int count = G_COUNTS[e];
    int row0 = blockIdx.y * 128;
    if (row0 >= count) return;
    int col0 = blockIdx.x * 128;

    int t = threadIdx.x;
    if (t < 128) {
        int gr = row0 + t;
        int idx = gr < count ? gr : count - 1;
        s_tok[t] = g_tokidx[e * CAP + idx];
        s_w[t]   = (gr < count) ? g_tokw[e * CAP + idx] : 0.0f;
    }
    __syncthreads();

    int lane = t & 31, wid = t >> 5;
    int warp_m = wid >> 2, warp_n = wid & 3;
    int gid = lane >> 2, tig = lane & 3;
    int lrow = (lane & 7) + (lane & 8);
    int lk   = ((lane >> 4) & 1) * 8;

    uint32_t sb = smem_u32(smem);

    const unsigned* he  = g_hh + ((size_t)e * CAP + row0) * (D_FF / 2);
    const unsigned* w2e = g_w2h + (size_t)e * (D_FF * D_MODEL / 2) + col0 / 2;

    const unsigned* aS[4]; uint32_t aD[4];
    const unsigned* bS[4]; uint32_t bD[4];
#pragma unroll
    for (int i = 0; i < 4; i++) {
        int cid = t + 256 * i;
        int arow = cid >> 3, ach = cid & 7;
        aS[i] = he + (size_t)arow * (D_FF / 2) + ach * 4;
        aD[i] = sb + OFFA(0) + arow * APITCH + ach * 16;
        int brow = cid >> 4, bch = cid & 15;
        bS[i] = w2e + (size_t)brow * (D_MODEL / 2) + bch * 4;
        bD[i] = sb + OFFB(0) + brow * BPITCH + bch * 16;
    }

    float acc[4][4][4];
#pragma unroll
    for (int i = 0; i < 4; i++)
#pragma unroll
        for (int j = 0; j < 4; j++)
#pragma unroll
            for (int q = 0; q < 4; q++) acc[i][j][q] = 0.0f;

#pragma unroll
    for (int i = 0; i < 4; i++) { cp16(aD[i], aS[i]); cp16(bD[i], bS[i]); }
    CP_COMMIT();

    const int NIT = D_FF / BK;   // 64
    int buf = 0;
    for (int it = 0; it < NIT; it++) {
        CP_WAIT0();
        __syncthreads();
        if (it + 1 < NIT) {
            int ktw = (it + 1) * (BK / 2);
            uint32_t as = (buf ^ 1) * ABYTES;
            uint32_t bs = (buf ^ 1) * BBYTES;
#pragma unroll
            for (int i = 0; i < 4; i++) {
                cp16(aD[i] + as, aS[i] + ktw);
                cp16(bD[i] + bs, bS[i] + (size_t)(it + 1) * BK * (D_MODEL / 2));
            }
            CP_COMMIT();
        }

        uint32_t sbA = sb + OFFA(buf);
        uint32_t sbB = sb + OFFB(buf);
#pragma unroll
        for (int ks = 0; ks < BK; ks += 16) {
            unsigned af[4][4], bf[4][2];
#pragma unroll
            for (int i = 0; i < 4; i++) {
                int m = warp_m * 64 + i * 16;
                uint32_t ad = sbA + (m + lrow) * APITCH + (ks + lk) * 2;
                LDMX4(af[i][0], af[i][1], af[i][2], af[i][3], ad);
            }
#pragma unroll
            for (int jj = 0; jj < 2; jj++) {
                uint32_t bd = sbB + (ks + lrow) * BPITCH
                            + (warp_n * 32 + jj * 16 + lk) * 2;
                LDMX4T(bf[jj*2][0], bf[jj*2][1], bf[jj*2+1][0], bf[jj*2+1][1], bd);
            }
#pragma unroll
            for (int i = 0; i < 4; i++)
#pragma unroll
                for (int j = 0; j < 4; j++)
                    mma_f16(acc[i][j], af[i][0], af[i][1], af[i][2], af[i][3],
                            bf[j][0], bf[j][1]);
        }
        buf ^= 1;
    }

#pragma unroll
    for (int i = 0; i < 4; i++) {
        int mrow = warp_m * 64 + i * 16 + gid;
#pragma unroll
        for (int half = 0; half < 2; half++) {
            int r = mrow + half * 8;
            int gr = row0 + r;
            if (gr >= count) continue;
            int tok = s_tok[r];
            float w  = s_w[r];
            float* orow = out + (size_t)tok * D_MODEL + col0;
#pragma unroll
            for (int j = 0; j < 4; j++) {
                int c = warp_n * 32 + j * 8 + tig * 2;
                float v0 = acc[i][j][half * 2 + 0] + b2[e * D_MODEL + col0 + c];
                float v1 = acc[i][j][half * 2 + 1] + b2[e * D_MODEL + col0 + c + 1];
                atomicAdd(&orow[c],     w * v0);
                atomicAdd(&orow[c + 1], w * v1);
            }
        }
    }
}

// ---------------- launch ----------------
extern "C" void kernel_launch(void* const* d_in, const int* in_sizes, int n_in,
                              void* d_out, int out_size) {
    const float* x  = (const float*)d_in[0];
    const float* rw = (const float*)d_in[1];
    const float* rb = (const float*)d_in[2];
    const float* w1 = (const float*)d_in[3];
    const float* b1 = (const float*)d_in[4];
    const float* w2 = (const float*)d_in[5];
    const float* b2 = (const float*)d_in[6];
    float* out = (float*)d_out;

    int T = in_sizes[0] / D_MODEL;

    cudaFuncSetAttribute(ffn1_kernel, cudaFuncAttributeMaxDynamicSharedMemorySize, DYN_BYTES);
    cudaFuncSetAttribute(ffn2_kernel, cudaFuncAttributeMaxDynamicSharedMemorySize, DYN_BYTES);

    // 1) zero control block (counts + sumprobs) — single 64B memset node
    void* ctrlp = nullptr;
    cudaGetSymbolAddress(&ctrlp, g_ctrl);
    cudaMemsetAsync(ctrlp, 0, 64);

    // 2) merged router + conversion (router blocks first -> overlap with conv)
    int nRouterBlocks = (T + 7) / 8;
    conv_router_kernel<<<nRouterBlocks + 8192, 256>>>(
        x, rw, rb, w1, w2, out, T, nRouterBlocks,
        (size_t)T * D_MODEL / 4, (size_t)NE * D_MODEL * D_FF / 4);

    // 3) ffn1 (+ aux loss)
    float* aux_ptr = (out_size > T * D_MODEL) ? (out + (size_t)T * D_MODEL) : nullptr;
    dim3 g1(D_FF / 128, CAP / 128, NE);
    ffn1_kernel<<<g1, 256, DYN_BYTES>>>(b1, aux_ptr, 1.0f / (float)T);

    // 4) ffn2
    dim3 g2(D_MODEL / 128, CAP / 128, NE);
    ffn2_kernel<<<g2, 256, DYN_BYTES>>>(b2, out);
}